// round 14
// baseline (speedup 1.0000x reference)
#include <cuda_runtime.h>
#include <cuda_fp16.h>
#include <cstdint>

// Problem dims
#define T_DIM 2048
#define B_DIM 16
#define D_DIM 1024
#define BD    16384            // B*D
#define M_DIM 32768            // T*B

// ---------------------------------------------------------------------------
// Scratch (device globals: allocation-free)
// ---------------------------------------------------------------------------
__device__ __half g_wh[(size_t)M_DIM * D_DIM];    // fp16 (1 - alpha)
__device__ __half g_vh[(size_t)M_DIM * D_DIM];    // fp16 v
__device__ __half g_wah[(size_t)D_DIM * D_DIM];   // fp16 W_alpha
__device__ __half g_wxh[(size_t)D_DIM * D_DIM];   // fp16 W_x
__device__ unsigned g_flags[256];                 // per-m-tile completion (16 each)

// ---------------------------------------------------------------------------
// Helpers
// ---------------------------------------------------------------------------
__device__ __forceinline__ uint32_t smem_u32(const void* p) {
    uint32_t a;
    asm("{ .reg .u64 t; cvta.to.shared.u64 t, %1; cvt.u32.u64 %0, t; }"
        : "=r"(a) : "l"(p));
    return a;
}

__device__ __forceinline__ void cp_async16(uint32_t dst, const void* src) {
    asm volatile("cp.async.cg.shared.global [%0], [%1], 16;"
                 :: "r"(dst), "l"(src) : "memory");
}
__device__ __forceinline__ void cp_commit() {
    asm volatile("cp.async.commit_group;" ::: "memory");
}
template <int N>
__device__ __forceinline__ void cp_wait() {
    asm volatile("cp.async.wait_group %0;" :: "n"(N) : "memory");
}

__device__ __forceinline__ void ldsm4(uint32_t& d0, uint32_t& d1, uint32_t& d2,
                                      uint32_t& d3, uint32_t addr) {
    asm volatile("ldmatrix.sync.aligned.m8n8.x4.shared.b16 {%0,%1,%2,%3}, [%4];"
                 : "=r"(d0), "=r"(d1), "=r"(d2), "=r"(d3)
                 : "r"(addr) : "memory");
}

__device__ __forceinline__ void mma_f16_f32(float* c, const uint32_t* a,
                                            const uint32_t* b) {
    asm volatile(
        "mma.sync.aligned.m16n8k16.row.col.f32.f16.f16.f32 "
        "{%0,%1,%2,%3}, {%4,%5,%6,%7}, {%8,%9}, {%0,%1,%2,%3};"
        : "+f"(c[0]), "+f"(c[1]), "+f"(c[2]), "+f"(c[3])
        : "r"(a[0]), "r"(a[1]), "r"(a[2]), "r"(a[3]), "r"(b[0]), "r"(b[1]));
}

__device__ __forceinline__ float fsigmoid(float z) {
    return __fdividef(1.0f, 1.0f + __expf(-z));
}
__device__ __forceinline__ float ftanh_fast(float z) {
    return 1.0f - __fdividef(2.0f, 1.0f + __expf(2.0f * z));
}
__device__ __forceinline__ float tanh_hw(float x) {
    float y;
    asm("tanh.approx.f32 %0, %1;" : "=f"(y) : "f"(x));
    return y;
}

// ---------------------------------------------------------------------------
// Weights fp32 -> fp16; block 0 also zeroes the m-tile flags for this run.
// ---------------------------------------------------------------------------
__global__ __launch_bounds__(256) void cvt_w_kernel(const float4* __restrict__ wa,
                                                    const float4* __restrict__ wx) {
    const int i = (int)blockIdx.x * 256 + (int)threadIdx.x;   // n4 = 262144
    if (blockIdx.x == 0) g_flags[threadIdx.x] = 0u;
    float4 v = wa[i];
    __half2 a = __float22half2_rn(make_float2(v.x, v.y));
    __half2 b = __float22half2_rn(make_float2(v.z, v.w));
    uint2 u; u.x = *(uint32_t*)&a; u.y = *(uint32_t*)&b;
    reinterpret_cast<uint2*>(g_wah)[i] = u;
    v = wx[i];
    a = __float22half2_rn(make_float2(v.x, v.y));
    b = __float22half2_rn(make_float2(v.z, v.w));
    u.x = *(uint32_t*)&a; u.y = *(uint32_t*)&b;
    reinterpret_cast<uint2*>(g_wxh)[i] = u;
}

// ---------------------------------------------------------------------------
// fp16 GEMM (R11 numerics: fp32 accumulators both paths).
// CTA 128x128, BK=32, 4 stages, 8 warps (2m x 4n), warp 64x32, m16n8k16.
// A (X): fp32 LDG -> half2 cvt at load (8 staging regs) -> STS.128 at loop
// tail. B (W): cp.async fp16. __maxnreg__(112): 2 GEMM CTAs + 1 scan CTA
// co-reside per SM (2*256*112 + 128*~55 < 64K regs; smem 2*80K + 24K < 228K).
// On completion each CTA releases g_flags[blockIdx.y] (16 arrivals per tile).
// ---------------------------------------------------------------------------
#define NKT      32            // 1024 / 32
#define ROWB     80            // 32 halves + 8 pad
#define A_BYTES  (128 * ROWB)  // 10240
#define STAGE_B  (2 * A_BYTES) // 20480
#define NSTAGE   4
#define GEMM_SMEM (NSTAGE * STAGE_B)   // 81920

__global__ void __maxnreg__(112) gemm_f16_kernel(
    const float* __restrict__ X,
    const float* __restrict__ ba, const float* __restrict__ bv)
{
    extern __shared__ char smem_raw[];
    const uint32_t sbase = smem_u32(smem_raw);

    const int tid  = (int)threadIdx.x;
    const int warp = tid >> 5;
    const int lane = tid & 31;
    const int wm   = warp >> 2;            // 0..1
    const int wn   = warp & 3;             // 0..3

    const int nm  = (int)blockIdx.x;       // 0..15
    const int mat = nm >> 3;
    const int n0  = (nm & 7) * 128;
    const int m0  = (int)blockIdx.y * 128;

    const __half* __restrict__ Wh  = mat ? g_wxh : g_wah;
    const float* __restrict__ bias = mat ? bv : ba;
    __half* __restrict__ outp      = mat ? g_vh : g_wh;

    const int r0 = tid >> 2;               // 0..63
    const int q0 = tid & 3;

    const float4* __restrict__ Xv = reinterpret_cast<const float4*>(X);

    // LDG fp32 + immediate cvt to half2 (staging = 8 regs, not 16)
    auto ldg_A = [&](int kt, uint32_t* r) {
        const size_t base = (size_t)(m0 + r0) * 256 + (size_t)(kt * 8 + q0 * 2);
        const float4 a = __ldg(Xv + base);
        const float4 b = __ldg(Xv + base + 1);
        const float4 c = __ldg(Xv + base + (size_t)64 * 256);
        const float4 d = __ldg(Xv + base + (size_t)64 * 256 + 1);
        __half2 h;
        h = __float22half2_rn(make_float2(a.x, a.y)); r[0] = *(uint32_t*)&h;
        h = __float22half2_rn(make_float2(a.z, a.w)); r[1] = *(uint32_t*)&h;
        h = __float22half2_rn(make_float2(b.x, b.y)); r[2] = *(uint32_t*)&h;
        h = __float22half2_rn(make_float2(b.z, b.w)); r[3] = *(uint32_t*)&h;
        h = __float22half2_rn(make_float2(c.x, c.y)); r[4] = *(uint32_t*)&h;
        h = __float22half2_rn(make_float2(c.z, c.w)); r[5] = *(uint32_t*)&h;
        h = __float22half2_rn(make_float2(d.x, d.y)); r[6] = *(uint32_t*)&h;
        h = __float22half2_rn(make_float2(d.z, d.w)); r[7] = *(uint32_t*)&h;
    };
    auto sts_A = [&](int kt, const uint32_t* r) {
        const uint32_t st = sbase + (uint32_t)(kt % NSTAGE) * STAGE_B;
        asm volatile("st.shared.v4.b32 [%0], {%1,%2,%3,%4};"
                     :: "r"(st + (uint32_t)(r0 * ROWB + q0 * 16)),
                        "r"(r[0]), "r"(r[1]), "r"(r[2]), "r"(r[3]) : "memory");
        asm volatile("st.shared.v4.b32 [%0], {%1,%2,%3,%4};"
                     :: "r"(st + (uint32_t)((r0 + 64) * ROWB + q0 * 16)),
                        "r"(r[4]), "r"(r[5]), "r"(r[6]), "r"(r[7]) : "memory");
    };
    auto load_B = [&](int kt) {
        const uint32_t st = sbase + (uint32_t)(kt % NSTAGE) * STAGE_B;
        const __half* wb = Wh + (size_t)(n0 + r0) * 1024 + kt * 32 + q0 * 8;
        cp_async16(st + A_BYTES + (uint32_t)(r0 * ROWB + q0 * 16), wb);
        cp_async16(st + A_BYTES + (uint32_t)((r0 + 64) * ROWB + q0 * 16),
                   wb + (size_t)64 * 1024);
    };

    // ldmatrix lane geometry (canonical m16n8k16)
    const int rA = lane & 15;
    const int cA = (lane >> 4) * 16;
    const int rB = (lane & 7) + ((lane >> 4) << 3);
    const int cB = ((lane >> 3) & 1) * 16;
    const uint32_t aBase = sbase + (uint32_t)((wm * 64 + rA) * ROWB + cA);
    const uint32_t bBase = sbase + A_BYTES + (uint32_t)((wn * 32 + rB) * ROWB + cB);

    float acc[4][4][4];
#pragma unroll
    for (int mf = 0; mf < 4; ++mf)
#pragma unroll
        for (int nf = 0; nf < 4; ++nf)
#pragma unroll
            for (int q = 0; q < 4; ++q) acc[mf][nf][q] = 0.0f;

    uint32_t pre[8];

    // prologue: stages 0..2 in flight, 0..1 complete before loop
    ldg_A(0, pre); load_B(0); cp_commit(); sts_A(0, pre);
    ldg_A(1, pre); load_B(1); cp_commit(); sts_A(1, pre);
    ldg_A(2, pre); load_B(2); cp_commit(); sts_A(2, pre);
    cp_wait<2>();
    __syncthreads();

    for (int kt = 0; kt < NKT; ++kt) {
        if (kt + 3 < NKT) { ldg_A(kt + 3, pre); load_B(kt + 3); cp_commit(); }

        const uint32_t soff = (uint32_t)(kt % NSTAGE) * STAGE_B;
        const uint32_t sa = aBase + soff;
        const uint32_t sb = bBase + soff;
#pragma unroll
        for (int ks = 0; ks < 2; ++ks) {
            uint32_t af[4][4];
#pragma unroll
            for (int mf = 0; mf < 4; ++mf)
                ldsm4(af[mf][0], af[mf][1], af[mf][2], af[mf][3],
                      sa + (uint32_t)(mf * 16 * ROWB + ks * 32));
            uint32_t bf[4][2];
#pragma unroll
            for (int p = 0; p < 2; ++p)
                ldsm4(bf[2 * p][0], bf[2 * p][1], bf[2 * p + 1][0],
                      bf[2 * p + 1][1], sb + (uint32_t)(p * 16 * ROWB + ks * 32));
#pragma unroll
            for (int mf = 0; mf < 4; ++mf)
#pragma unroll
                for (int nf = 0; nf < 4; ++nf)
                    mma_f16_f32(acc[mf][nf], af[mf], bf[nf]);
        }

        if (kt + 3 < NKT) sts_A(kt + 3, pre);   // buffer (kt+3)%4 == (kt-1)%4

        if (kt + 1 < NKT) {
            if (kt + 3 < NKT)      cp_wait<2>();
            else if (kt + 2 < NKT) cp_wait<1>();
            else                   cp_wait<0>();
            __syncthreads();
        }
    }

    // epilogue: bias + activation, half2 stores
    const int g   = lane >> 2;
    const int tig = lane & 3;
#pragma unroll
    for (int mf = 0; mf < 4; ++mf) {
#pragma unroll
        for (int nf = 0; nf < 4; ++nf) {
            const int row = m0 + wm * 64 + mf * 16 + g;
            const int col = n0 + wn * 32 + nf * 8 + 2 * tig;
            const float bb0 = __ldg(&bias[col]);
            const float bb1 = __ldg(&bias[col + 1]);
            float z00 = acc[mf][nf][0] + bb0;
            float z01 = acc[mf][nf][1] + bb1;
            float z10 = acc[mf][nf][2] + bb0;
            float z11 = acc[mf][nf][3] + bb1;
            float2 o0, o1;
            if (mat == 0) {        // store w = 1 - alpha = sigmoid(-z)
                o0 = make_float2(fsigmoid(-z00), fsigmoid(-z01));
                o1 = make_float2(fsigmoid(-z10), fsigmoid(-z11));
            } else {               // store v = tanh(z)
                o0 = make_float2(ftanh_fast(z00), ftanh_fast(z01));
                o1 = make_float2(ftanh_fast(z10), ftanh_fast(z11));
            }
            *(__half2*)(outp + (size_t)row * D_DIM + col)       = __float22half2_rn(o0);
            *(__half2*)(outp + (size_t)(row + 8) * D_DIM + col) = __float22half2_rn(o1);
        }
    }

    // release: this m-tile's outputs are globally visible, then count arrival
    __syncthreads();
    if (tid == 0) {
        __threadfence();
        atomicAdd(&g_flags[blockIdx.y], 1u);
    }
}

// ---------------------------------------------------------------------------
// Sequential scan, overlapped with the GEMM via per-m-tile flags: stage b
// (timesteps 8b..8b+7) waits for g_flags[b] == 16 before its cp.async loads.
// 128 CTAs x 128 threads, warp-autonomous rings, HW tanh.approx sigmoids.
// ---------------------------------------------------------------------------
#define SC_STEPS  8
#define SC_STG    6
#define SC_WARPS  4

__global__ __launch_bounds__(128) void scan_kernel(
    const float* __restrict__ h0,
    const float* __restrict__ dg, const float* __restrict__ bg,
    float* __restrict__ out, float* __restrict__ hout)
{
    __shared__ __align__(16) __half sbuf[SC_WARPS][SC_STG][2][SC_STEPS][32]; // 24KB

    const int tid  = (int)threadIdx.x;
    const int w    = tid >> 5;
    const int lane = tid & 31;
    const int cbase = (int)blockIdx.x * 128 + w * 32;
    const int idx   = cbase + lane;
    const int d     = idx & (D_DIM - 1);

    const float hc1 = 0.5f * dg[d];       // gate = 0.5 + 0.5*tanh(0.5*(c1*h+c0))
    const float hc0 = 0.5f * bg[d];

    float h = h0[idx];
    hout[idx] = h;

    const __half* __restrict__ Wp = g_wh;
    const __half* __restrict__ V  = g_vh;
    const uint32_t sw0 = smem_u32(&sbuf[w][0][0][0][0]);

    auto load_stage = [&](int b) {
        // acquire: wait until all 16 GEMM CTAs of m-tile b have released
        if (lane == 0) {
            while (*(volatile unsigned*)&g_flags[b] < 16u) __nanosleep(200);
        }
        __syncwarp();
        __threadfence();
        const uint32_t st = sw0 + (uint32_t)(b % SC_STG) * 1024u;
        const int t0 = b * SC_STEPS;
#pragma unroll
        for (int j = 0; j < 2; ++j) {
            const int c    = lane + 32 * j;
            const int arr  = c >> 5;              // 0=W, 1=V
            const int wch  = c & 31;
            const int step = wch >> 2;
            const int part = wch & 3;
            const __half* src = (arr ? V : Wp) + (size_t)(t0 + step) * BD
                                + cbase + part * 8;
            cp_async16(st + (uint32_t)(arr * 512 + step * 64 + part * 16), src);
        }
        cp_commit();
    };

#pragma unroll
    for (int s = 0; s < SC_STG - 1; ++s) load_stage(s);

    const int NB = T_DIM / SC_STEPS;      // 256
    for (int b = 0; b < NB; ++b) {
        cp_wait<SC_STG - 2>();
        __syncwarp();

        const __half* sW = &sbuf[w][b % SC_STG][0][0][0];
        const __half* sV = &sbuf[w][b % SC_STG][1][0][0];

        float a[SC_STEPS], wv[SC_STEPS];
#pragma unroll
        for (int i = 0; i < SC_STEPS; ++i) {
            const float wq = __half2float(sW[i * 32 + lane]);
            const float v  = __half2float(sV[i * 32 + lane]);
            a[i]  = 1.0f - wq;
            wv[i] = wq * v;
        }
        __syncwarp();

        if (b + SC_STG - 1 < NB) load_stage(b + SC_STG - 1);
        else cp_commit();

        const int t0 = b * SC_STEPS;
#pragma unroll
        for (int i = 0; i < SC_STEPS; ++i) {
            const float tg = tanh_hw(fmaf(hc1, h, hc0));
            const float gg = fmaf(0.5f, tg, 0.5f);
            h = fmaf(a[i], h, wv[i] * gg);
            const float sg = fmaf(0.5f, tanh_hw(0.5f * h), 0.5f);
            __stcs(&out[(size_t)(t0 + i) * BD + idx], h * h * sg);
            __stcs(&hout[(size_t)(t0 + i + 1) * BD + idx], h);
        }
    }
}

// ---------------------------------------------------------------------------
// Launch: cvt_w -> fork { GEMM on stream 0 || scan on s2 } -> join.
// Standard capture-legal event fork-join; flags provide data ordering.
// ---------------------------------------------------------------------------
extern "C" void kernel_launch(void* const* d_in, const int* in_sizes, int n_in,
                              void* d_out, int out_size)
{
    (void)in_sizes; (void)n_in; (void)out_size;
    const float* x  = (const float*)d_in[0];   // [T,B,D]
    const float* h0 = (const float*)d_in[1];   // [B,D]
    const float* Wa = (const float*)d_in[2];   // [D,D]
    const float* ba = (const float*)d_in[3];   // [D]
    const float* Wx = (const float*)d_in[4];   // [D,D]
    const float* bv = (const float*)d_in[5];   // [D]
    const float* dg = (const float*)d_in[6];   // [D]
    const float* bg = (const float*)d_in[7];   // [D]

    float* out  = (float*)d_out;
    float* hout = out + (size_t)T_DIM * BD;

    static cudaStream_t s2 = nullptr;
    static cudaEvent_t ev_fork = nullptr, ev_join = nullptr;
    if (s2 == nullptr) {
        cudaStreamCreateWithFlags(&s2, cudaStreamNonBlocking);
        cudaEventCreateWithFlags(&ev_fork, cudaEventDisableTiming);
        cudaEventCreateWithFlags(&ev_join, cudaEventDisableTiming);
    }

    cudaFuncSetAttribute(gemm_f16_kernel,
                         cudaFuncAttributeMaxDynamicSharedMemorySize, GEMM_SMEM);

    // 1. weights fp32 -> fp16 + flag reset (stream 0)
    cvt_w_kernel<<<(D_DIM * D_DIM / 4) / 256, 256>>>((const float4*)Wa,
                                                     (const float4*)Wx);

    // fork: scan runs concurrently with the GEMM, paced by g_flags
    cudaEventRecord(ev_fork, 0);
    cudaStreamWaitEvent(s2, ev_fork, 0);

    // 2. dual projections (stream 0; x-fast: 16 CTAs share X m-tile via L2)
    dim3 grid(16, M_DIM / 128, 1);
    gemm_f16_kernel<<<grid, 256, GEMM_SMEM>>>(x, ba, bv);

    // 3. recurrence scan (forked stream)
    scan_kernel<<<BD / 128, 128, 0, s2>>>(h0, dg, bg, out, hout);

    // join
    cudaEventRecord(ev_join, s2);
    cudaStreamWaitEvent(0, ev_join, 0);
}

// round 15
// speedup vs baseline: 1.9076x; 1.9076x over previous
#include <cuda_runtime.h>
#include <cuda_fp16.h>
#include <cstdint>

// Problem dims
#define T_DIM 2048
#define B_DIM 16
#define D_DIM 1024
#define BD    16384            // B*D
#define M_DIM 32768            // T*B

// ---------------------------------------------------------------------------
// Scratch (device globals: allocation-free)
// g_wh stores w = 1 - alpha = sigmoid(-z): near 0.12 the fp16 grid is ~4x
// finer than near alpha~0.88, cutting the recurrence's dominant error term.
// ---------------------------------------------------------------------------
__device__ __half g_wh[(size_t)M_DIM * D_DIM];    // fp16 (1 - alpha)
__device__ __half g_vh[(size_t)M_DIM * D_DIM];    // fp16 v
__device__ __half g_wah[(size_t)D_DIM * D_DIM];   // fp16 W_alpha
__device__ __half g_wxh[(size_t)D_DIM * D_DIM];   // fp16 W_x

// ---------------------------------------------------------------------------
// Helpers
// ---------------------------------------------------------------------------
__device__ __forceinline__ uint32_t smem_u32(const void* p) {
    uint32_t a;
    asm("{ .reg .u64 t; cvta.to.shared.u64 t, %1; cvt.u32.u64 %0, t; }"
        : "=r"(a) : "l"(p));
    return a;
}

__device__ __forceinline__ void cp_async16(uint32_t dst, const void* src) {
    asm volatile("cp.async.cg.shared.global [%0], [%1], 16;"
                 :: "r"(dst), "l"(src) : "memory");
}
__device__ __forceinline__ void cp_commit() {
    asm volatile("cp.async.commit_group;" ::: "memory");
}
template <int N>
__device__ __forceinline__ void cp_wait() {
    asm volatile("cp.async.wait_group %0;" :: "n"(N) : "memory");
}

__device__ __forceinline__ void ldsm4(uint32_t& d0, uint32_t& d1, uint32_t& d2,
                                      uint32_t& d3, uint32_t addr) {
    asm volatile("ldmatrix.sync.aligned.m8n8.x4.shared.b16 {%0,%1,%2,%3}, [%4];"
                 : "=r"(d0), "=r"(d1), "=r"(d2), "=r"(d3)
                 : "r"(addr) : "memory");
}

__device__ __forceinline__ void mma_f16_f32(float* c, const uint32_t* a,
                                            const uint32_t* b) {
    asm volatile(
        "mma.sync.aligned.m16n8k16.row.col.f32.f16.f16.f32 "
        "{%0,%1,%2,%3}, {%4,%5,%6,%7}, {%8,%9}, {%0,%1,%2,%3};"
        : "+f"(c[0]), "+f"(c[1]), "+f"(c[2]), "+f"(c[3])
        : "r"(a[0]), "r"(a[1]), "r"(a[2]), "r"(a[3]), "r"(b[0]), "r"(b[1]));
}

__device__ __forceinline__ float fsigmoid(float z) {
    return __fdividef(1.0f, 1.0f + __expf(-z));
}
__device__ __forceinline__ float ftanh_fast(float z) {
    return 1.0f - __fdividef(2.0f, 1.0f + __expf(2.0f * z));
}
__device__ __forceinline__ float tanh_hw(float x) {
    float y;
    asm("tanh.approx.f32 %0, %1;" : "=f"(y) : "f"(x));
    return y;
}

// ---------------------------------------------------------------------------
// fp32 -> fp16 conversion for the two weight matrices (X converts in-GEMM)
// ---------------------------------------------------------------------------
__global__ __launch_bounds__(256) void cvt_w_kernel(const float4* __restrict__ wa,
                                                    const float4* __restrict__ wx) {
    const int i = (int)blockIdx.x * 256 + (int)threadIdx.x;   // n4 = 262144
    float4 v = wa[i];
    __half2 a = __float22half2_rn(make_float2(v.x, v.y));
    __half2 b = __float22half2_rn(make_float2(v.z, v.w));
    uint2 u; u.x = *(uint32_t*)&a; u.y = *(uint32_t*)&b;
    reinterpret_cast<uint2*>(g_wah)[i] = u;
    v = wx[i];
    a = __float22half2_rn(make_float2(v.x, v.y));
    b = __float22half2_rn(make_float2(v.z, v.w));
    u.x = *(uint32_t*)&a; u.y = *(uint32_t*)&b;
    reinterpret_cast<uint2*>(g_wxh)[i] = u;
}

// ---------------------------------------------------------------------------
// fp16 GEMM (R11-verified config): C[m,e] = sum_d X[m,d]*W[e,d] (+bias,+act).
// CTA 128x128, BK=32, 4 stages, 8 warps (2m x 4n), warp 64x32, m16n8k16,
// fp32 accumulators. A (X): fp32 LDG -> reg cvt -> STS.128 (no cvt_x pass).
// B (W): cp.async fp16. No register cap (124 regs, 2 CTAs/SM by smem).
// mat==0 stores w = sigmoid(-z) = 1 - alpha; mat==1 stores tanh(z), fp16.
// blockIdx.x in [0,16): bit3 = matrix, bits[2:0] = n-tile (x-fast: 16 CTAs
// share each X m-tile via L2).
// ---------------------------------------------------------------------------
#define NKT      32            // 1024 / 32
#define ROWB     80            // 32 halves + 8 pad
#define A_BYTES  (128 * ROWB)  // 10240
#define STAGE_B  (2 * A_BYTES) // 20480
#define NSTAGE   4
#define GEMM_SMEM (NSTAGE * STAGE_B)   // 81920

__global__ __launch_bounds__(256, 2) void gemm_f16_kernel(
    const float* __restrict__ X,
    const float* __restrict__ ba, const float* __restrict__ bv)
{
    extern __shared__ char smem_raw[];
    const uint32_t sbase = smem_u32(smem_raw);

    const int tid  = (int)threadIdx.x;
    const int warp = tid >> 5;
    const int lane = tid & 31;
    const int wm   = warp >> 2;            // 0..1
    const int wn   = warp & 3;             // 0..3

    const int nm  = (int)blockIdx.x;       // 0..15
    const int mat = nm >> 3;
    const int n0  = (nm & 7) * 128;
    const int m0  = (int)blockIdx.y * 128;

    const __half* __restrict__ Wh  = mat ? g_wxh : g_wah;
    const float* __restrict__ bias = mat ? bv : ba;
    __half* __restrict__ outp      = mat ? g_vh : g_wh;

    const int r0 = tid >> 2;               // 0..63
    const int q0 = tid & 3;

    const float4* __restrict__ Xv = reinterpret_cast<const float4*>(X);

    auto ldg_A = [&](int kt, float4* r) {
        const size_t base = (size_t)(m0 + r0) * 256 + (size_t)(kt * 8 + q0 * 2);
        r[0] = __ldg(Xv + base);
        r[1] = __ldg(Xv + base + 1);
        r[2] = __ldg(Xv + base + (size_t)64 * 256);
        r[3] = __ldg(Xv + base + (size_t)64 * 256 + 1);
    };
    auto sts_A = [&](int kt, const float4* r) {
        const uint32_t st = sbase + (uint32_t)(kt % NSTAGE) * STAGE_B;
        __half2 ha = __float22half2_rn(make_float2(r[0].x, r[0].y));
        __half2 hb = __float22half2_rn(make_float2(r[0].z, r[0].w));
        __half2 hc = __float22half2_rn(make_float2(r[1].x, r[1].y));
        __half2 hd = __float22half2_rn(make_float2(r[1].z, r[1].w));
        asm volatile("st.shared.v4.b32 [%0], {%1,%2,%3,%4};"
                     :: "r"(st + (uint32_t)(r0 * ROWB + q0 * 16)),
                        "r"(*(uint32_t*)&ha), "r"(*(uint32_t*)&hb),
                        "r"(*(uint32_t*)&hc), "r"(*(uint32_t*)&hd) : "memory");
        ha = __float22half2_rn(make_float2(r[2].x, r[2].y));
        hb = __float22half2_rn(make_float2(r[2].z, r[2].w));
        hc = __float22half2_rn(make_float2(r[3].x, r[3].y));
        hd = __float22half2_rn(make_float2(r[3].z, r[3].w));
        asm volatile("st.shared.v4.b32 [%0], {%1,%2,%3,%4};"
                     :: "r"(st + (uint32_t)((r0 + 64) * ROWB + q0 * 16)),
                        "r"(*(uint32_t*)&ha), "r"(*(uint32_t*)&hb),
                        "r"(*(uint32_t*)&hc), "r"(*(uint32_t*)&hd) : "memory");
    };
    auto load_B = [&](int kt) {
        const uint32_t st = sbase + (uint32_t)(kt % NSTAGE) * STAGE_B;
        const __half* wb = Wh + (size_t)(n0 + r0) * 1024 + kt * 32 + q0 * 8;
        cp_async16(st + A_BYTES + (uint32_t)(r0 * ROWB + q0 * 16), wb);
        cp_async16(st + A_BYTES + (uint32_t)((r0 + 64) * ROWB + q0 * 16),
                   wb + (size_t)64 * 1024);
    };

    // ldmatrix lane geometry (canonical m16n8k16)
    const int rA = lane & 15;
    const int cA = (lane >> 4) * 16;
    const int rB = (lane & 7) + ((lane >> 4) << 3);
    const int cB = ((lane >> 3) & 1) * 16;
    const uint32_t aBase = sbase + (uint32_t)((wm * 64 + rA) * ROWB + cA);
    const uint32_t bBase = sbase + A_BYTES + (uint32_t)((wn * 32 + rB) * ROWB + cB);

    float acc[4][4][4];
#pragma unroll
    for (int mf = 0; mf < 4; ++mf)
#pragma unroll
        for (int nf = 0; nf < 4; ++nf)
#pragma unroll
            for (int q = 0; q < 4; ++q) acc[mf][nf][q] = 0.0f;

    float4 pre[4];

    // prologue: stages 0..2 in flight, 0..1 complete before loop
    ldg_A(0, pre); load_B(0); cp_commit(); sts_A(0, pre);
    ldg_A(1, pre); load_B(1); cp_commit(); sts_A(1, pre);
    ldg_A(2, pre); load_B(2); cp_commit(); sts_A(2, pre);
    cp_wait<2>();
    __syncthreads();

    for (int kt = 0; kt < NKT; ++kt) {
        if (kt + 3 < NKT) { ldg_A(kt + 3, pre); load_B(kt + 3); cp_commit(); }

        const uint32_t soff = (uint32_t)(kt % NSTAGE) * STAGE_B;
        const uint32_t sa = aBase + soff;
        const uint32_t sb = bBase + soff;
#pragma unroll
        for (int ks = 0; ks < 2; ++ks) {
            uint32_t af[4][4];
#pragma unroll
            for (int mf = 0; mf < 4; ++mf)
                ldsm4(af[mf][0], af[mf][1], af[mf][2], af[mf][3],
                      sa + (uint32_t)(mf * 16 * ROWB + ks * 32));
            uint32_t bf[4][2];
#pragma unroll
            for (int p = 0; p < 2; ++p)
                ldsm4(bf[2 * p][0], bf[2 * p][1], bf[2 * p + 1][0],
                      bf[2 * p + 1][1], sb + (uint32_t)(p * 16 * ROWB + ks * 32));
#pragma unroll
            for (int mf = 0; mf < 4; ++mf)
#pragma unroll
                for (int nf = 0; nf < 4; ++nf)
                    mma_f16_f32(acc[mf][nf], af[mf], bf[nf]);
        }

        if (kt + 3 < NKT) sts_A(kt + 3, pre);   // buffer (kt+3)%4 == (kt-1)%4

        if (kt + 1 < NKT) {
            if (kt + 3 < NKT)      cp_wait<2>();
            else if (kt + 2 < NKT) cp_wait<1>();
            else                   cp_wait<0>();
            __syncthreads();
        }
    }

    // epilogue: bias + activation, half2 stores
    const int g   = lane >> 2;
    const int tig = lane & 3;
#pragma unroll
    for (int mf = 0; mf < 4; ++mf) {
#pragma unroll
        for (int nf = 0; nf < 4; ++nf) {
            const int row = m0 + wm * 64 + mf * 16 + g;
            const int col = n0 + wn * 32 + nf * 8 + 2 * tig;
            const float bb0 = __ldg(&bias[col]);
            const float bb1 = __ldg(&bias[col + 1]);
            float z00 = acc[mf][nf][0] + bb0;
            float z01 = acc[mf][nf][1] + bb1;
            float z10 = acc[mf][nf][2] + bb0;
            float z11 = acc[mf][nf][3] + bb1;
            float2 o0, o1;
            if (mat == 0) {        // store w = 1 - alpha = sigmoid(-z)
                o0 = make_float2(fsigmoid(-z00), fsigmoid(-z01));
                o1 = make_float2(fsigmoid(-z10), fsigmoid(-z11));
            } else {               // store v = tanh(z)
                o0 = make_float2(ftanh_fast(z00), ftanh_fast(z01));
                o1 = make_float2(ftanh_fast(z10), ftanh_fast(z11));
            }
            *(__half2*)(outp + (size_t)row * D_DIM + col)       = __float22half2_rn(o0);
            *(__half2*)(outp + (size_t)(row + 8) * D_DIM + col) = __float22half2_rn(o1);
        }
    }
}

// ---------------------------------------------------------------------------
// Sequential scan (R11-verified config): 128 CTAs x 128 threads, each warp
// owns 32 channels with its own cp.async ring (6 stages x 8 steps =
// 1KB/stage/warp). Both sigmoids via HW tanh.approx; a = 1 - w reconstructed
// in fp32 from the finely-quantized fp16 w.
// ---------------------------------------------------------------------------
#define SC_STEPS  8
#define SC_STG    6
#define SC_WARPS  4

__global__ __launch_bounds__(128) void scan_kernel(
    const float* __restrict__ h0,
    const float* __restrict__ dg, const float* __restrict__ bg,
    float* __restrict__ out, float* __restrict__ hout)
{
    __shared__ __align__(16) __half sbuf[SC_WARPS][SC_STG][2][SC_STEPS][32]; // 24KB

    const int tid  = (int)threadIdx.x;
    const int w    = tid >> 5;
    const int lane = tid & 31;
    const int cbase = (int)blockIdx.x * 128 + w * 32;
    const int idx   = cbase + lane;
    const int d     = idx & (D_DIM - 1);

    const float hc1 = 0.5f * dg[d];       // gate = 0.5 + 0.5*tanh(0.5*(c1*h+c0))
    const float hc0 = 0.5f * bg[d];

    float h = h0[idx];
    hout[idx] = h;

    const __half* __restrict__ Wp = g_wh;
    const __half* __restrict__ V  = g_vh;
    const uint32_t sw0 = smem_u32(&sbuf[w][0][0][0][0]);

    auto load_stage = [&](int b) {
        const uint32_t st = sw0 + (uint32_t)(b % SC_STG) * 1024u;
        const int t0 = b * SC_STEPS;
#pragma unroll
        for (int j = 0; j < 2; ++j) {
            const int c    = lane + 32 * j;
            const int arr  = c >> 5;              // 0=W, 1=V
            const int wch  = c & 31;
            const int step = wch >> 2;
            const int part = wch & 3;
            const __half* src = (arr ? V : Wp) + (size_t)(t0 + step) * BD
                                + cbase + part * 8;
            cp_async16(st + (uint32_t)(arr * 512 + step * 64 + part * 16), src);
        }
        cp_commit();
    };

#pragma unroll
    for (int s = 0; s < SC_STG - 1; ++s) load_stage(s);

    const int NB = T_DIM / SC_STEPS;      // 256
    for (int b = 0; b < NB; ++b) {
        cp_wait<SC_STG - 2>();
        __syncwarp();

        const __half* sW = &sbuf[w][b % SC_STG][0][0][0];
        const __half* sV = &sbuf[w][b % SC_STG][1][0][0];

        float a[SC_STEPS], wv[SC_STEPS];
#pragma unroll
        for (int i = 0; i < SC_STEPS; ++i) {
            const float wq = __half2float(sW[i * 32 + lane]);
            const float v  = __half2float(sV[i * 32 + lane]);
            a[i]  = 1.0f - wq;
            wv[i] = wq * v;
        }
        __syncwarp();

        if (b + SC_STG - 1 < NB) load_stage(b + SC_STG - 1);
        else cp_commit();

        const int t0 = b * SC_STEPS;
#pragma unroll
        for (int i = 0; i < SC_STEPS; ++i) {
            const float tg = tanh_hw(fmaf(hc1, h, hc0));
            const float gg = fmaf(0.5f, tg, 0.5f);
            h = fmaf(a[i], h, wv[i] * gg);
            const float sg = fmaf(0.5f, tanh_hw(0.5f * h), 0.5f);
            __stcs(&out[(size_t)(t0 + i) * BD + idx], h * h * sg);
            __stcs(&hout[(size_t)(t0 + i + 1) * BD + idx], h);
        }
    }
}

// ---------------------------------------------------------------------------
// Launch (single stream — overlap measured unprofitable in R14)
// ---------------------------------------------------------------------------
extern "C" void kernel_launch(void* const* d_in, const int* in_sizes, int n_in,
                              void* d_out, int out_size)
{
    (void)in_sizes; (void)n_in; (void)out_size;
    const float* x  = (const float*)d_in[0];   // [T,B,D]
    const float* h0 = (const float*)d_in[1];   // [B,D]
    const float* Wa = (const float*)d_in[2];   // [D,D]
    const float* ba = (const float*)d_in[3];   // [D]
    const float* Wx = (const float*)d_in[4];   // [D,D]
    const float* bv = (const float*)d_in[5];   // [D]
    const float* dg = (const float*)d_in[6];   // [D]
    const float* bg = (const float*)d_in[7];   // [D]

    float* out  = (float*)d_out;
    float* hout = out + (size_t)T_DIM * BD;

    cudaFuncSetAttribute(gemm_f16_kernel,
                         cudaFuncAttributeMaxDynamicSharedMemorySize, GEMM_SMEM);

    // 1. weights fp32 -> fp16 (X converts inside the GEMM)
    cvt_w_kernel<<<(D_DIM * D_DIM / 4) / 256, 256>>>((const float4*)Wa,
                                                     (const float4*)Wx);

    // 2. dual projections (x-fast: 16 (n,mat) CTAs share X m-tile via L2)
    dim3 grid(16, M_DIM / 128, 1);
    gemm_f16_kernel<<<grid, 256, GEMM_SMEM>>>(x, ba, bv);

    // 3. recurrence scan
    scan_kernel<<<BD / 128, 128>>>(h0, dg, bg, out, hout);
}

// round 16
// speedup vs baseline: 1.9117x; 1.0021x over previous
#include <cuda_runtime.h>
#include <cuda_fp16.h>
#include <cstdint>

// Problem dims
#define T_DIM 2048
#define B_DIM 16
#define D_DIM 1024
#define BD    16384            // B*D
#define M_DIM 32768            // T*B

// ---------------------------------------------------------------------------
// Scratch (device globals: allocation-free)
// g_wh stores w = 1 - alpha = sigmoid(-z): near 0.12 the fp16 grid is ~4x
// finer than near alpha~0.88, cutting the recurrence's dominant error term.
// ---------------------------------------------------------------------------
__device__ __half g_wh[(size_t)M_DIM * D_DIM];    // fp16 (1 - alpha)
__device__ __half g_vh[(size_t)M_DIM * D_DIM];    // fp16 v
__device__ __half g_wah[(size_t)D_DIM * D_DIM];   // fp16 W_alpha
__device__ __half g_wxh[(size_t)D_DIM * D_DIM];   // fp16 W_x

// ---------------------------------------------------------------------------
// Helpers
// ---------------------------------------------------------------------------
__device__ __forceinline__ uint32_t smem_u32(const void* p) {
    uint32_t a;
    asm("{ .reg .u64 t; cvta.to.shared.u64 t, %1; cvt.u32.u64 %0, t; }"
        : "=r"(a) : "l"(p));
    return a;
}

__device__ __forceinline__ void cp_async16(uint32_t dst, const void* src) {
    asm volatile("cp.async.cg.shared.global [%0], [%1], 16;"
                 :: "r"(dst), "l"(src) : "memory");
}
__device__ __forceinline__ void cp_commit() {
    asm volatile("cp.async.commit_group;" ::: "memory");
}
template <int N>
__device__ __forceinline__ void cp_wait() {
    asm volatile("cp.async.wait_group %0;" :: "n"(N) : "memory");
}

__device__ __forceinline__ void ldsm4(uint32_t& d0, uint32_t& d1, uint32_t& d2,
                                      uint32_t& d3, uint32_t addr) {
    asm volatile("ldmatrix.sync.aligned.m8n8.x4.shared.b16 {%0,%1,%2,%3}, [%4];"
                 : "=r"(d0), "=r"(d1), "=r"(d2), "=r"(d3)
                 : "r"(addr) : "memory");
}

__device__ __forceinline__ void mma_f16_f32(float* c, const uint32_t* a,
                                            const uint32_t* b) {
    asm volatile(
        "mma.sync.aligned.m16n8k16.row.col.f32.f16.f16.f32 "
        "{%0,%1,%2,%3}, {%4,%5,%6,%7}, {%8,%9}, {%0,%1,%2,%3};"
        : "+f"(c[0]), "+f"(c[1]), "+f"(c[2]), "+f"(c[3])
        : "r"(a[0]), "r"(a[1]), "r"(a[2]), "r"(a[3]), "r"(b[0]), "r"(b[1]));
}

__device__ __forceinline__ float fsigmoid(float z) {
    return __fdividef(1.0f, 1.0f + __expf(-z));
}
__device__ __forceinline__ float ftanh_fast(float z) {
    return 1.0f - __fdividef(2.0f, 1.0f + __expf(2.0f * z));
}
__device__ __forceinline__ float tanh_hw(float x) {
    float y;
    asm("tanh.approx.f32 %0, %1;" : "=f"(y) : "f"(x));
    return y;
}

// ---------------------------------------------------------------------------
// fp32 -> fp16 conversion for the two weight matrices (X converts in-GEMM)
// ---------------------------------------------------------------------------
__global__ __launch_bounds__(256) void cvt_w_kernel(const float4* __restrict__ wa,
                                                    const float4* __restrict__ wx) {
    const int i = (int)blockIdx.x * 256 + (int)threadIdx.x;   // n4 = 262144
    float4 v = wa[i];
    __half2 a = __float22half2_rn(make_float2(v.x, v.y));
    __half2 b = __float22half2_rn(make_float2(v.z, v.w));
    uint2 u; u.x = *(uint32_t*)&a; u.y = *(uint32_t*)&b;
    reinterpret_cast<uint2*>(g_wah)[i] = u;
    v = wx[i];
    a = __float22half2_rn(make_float2(v.x, v.y));
    b = __float22half2_rn(make_float2(v.z, v.w));
    u.x = *(uint32_t*)&a; u.y = *(uint32_t*)&b;
    reinterpret_cast<uint2*>(g_wxh)[i] = u;
}

// ---------------------------------------------------------------------------
// fp16 GEMM (R11/R15-verified config): C[m,e] = sum_d X[m,d]*W[e,d] (+bias,
// +activation). CTA 128x128, BK=32, 4 stages, 8 warps (2m x 4n), warp 64x32,
// m16n8k16, fp32 accumulators. A (X): fp32 LDG -> reg cvt -> STS.128.
// B (W): cp.async fp16. mat==0 stores w = sigmoid(-z); mat==1 stores tanh(z).
// blockIdx.x in [0,16): bit3 = matrix, bits[2:0] = n-tile (x-fast: 16 CTAs
// share each X m-tile via L2).
// ---------------------------------------------------------------------------
#define NKT      32            // 1024 / 32
#define ROWB     80            // 32 halves + 8 pad
#define A_BYTES  (128 * ROWB)  // 10240
#define STAGE_B  (2 * A_BYTES) // 20480
#define NSTAGE   4
#define GEMM_SMEM (NSTAGE * STAGE_B)   // 81920

__global__ __launch_bounds__(256, 2) void gemm_f16_kernel(
    const float* __restrict__ X,
    const float* __restrict__ ba, const float* __restrict__ bv)
{
    extern __shared__ char smem_raw[];
    const uint32_t sbase = smem_u32(smem_raw);

    const int tid  = (int)threadIdx.x;
    const int warp = tid >> 5;
    const int lane = tid & 31;
    const int wm   = warp >> 2;            // 0..1
    const int wn   = warp & 3;             // 0..3

    const int nm  = (int)blockIdx.x;       // 0..15
    const int mat = nm >> 3;
    const int n0  = (nm & 7) * 128;
    const int m0  = (int)blockIdx.y * 128;

    const __half* __restrict__ Wh  = mat ? g_wxh : g_wah;
    const float* __restrict__ bias = mat ? bv : ba;
    __half* __restrict__ outp      = mat ? g_vh : g_wh;

    const int r0 = tid >> 2;               // 0..63
    const int q0 = tid & 3;

    const float4* __restrict__ Xv = reinterpret_cast<const float4*>(X);

    auto ldg_A = [&](int kt, float4* r) {
        const size_t base = (size_t)(m0 + r0) * 256 + (size_t)(kt * 8 + q0 * 2);
        r[0] = __ldg(Xv + base);
        r[1] = __ldg(Xv + base + 1);
        r[2] = __ldg(Xv + base + (size_t)64 * 256);
        r[3] = __ldg(Xv + base + (size_t)64 * 256 + 1);
    };
    auto sts_A = [&](int kt, const float4* r) {
        const uint32_t st = sbase + (uint32_t)(kt % NSTAGE) * STAGE_B;
        __half2 ha = __float22half2_rn(make_float2(r[0].x, r[0].y));
        __half2 hb = __float22half2_rn(make_float2(r[0].z, r[0].w));
        __half2 hc = __float22half2_rn(make_float2(r[1].x, r[1].y));
        __half2 hd = __float22half2_rn(make_float2(r[1].z, r[1].w));
        asm volatile("st.shared.v4.b32 [%0], {%1,%2,%3,%4};"
                     :: "r"(st + (uint32_t)(r0 * ROWB + q0 * 16)),
                        "r"(*(uint32_t*)&ha), "r"(*(uint32_t*)&hb),
                        "r"(*(uint32_t*)&hc), "r"(*(uint32_t*)&hd) : "memory");
        ha = __float22half2_rn(make_float2(r[2].x, r[2].y));
        hb = __float22half2_rn(make_float2(r[2].z, r[2].w));
        hc = __float22half2_rn(make_float2(r[3].x, r[3].y));
        hd = __float22half2_rn(make_float2(r[3].z, r[3].w));
        asm volatile("st.shared.v4.b32 [%0], {%1,%2,%3,%4};"
                     :: "r"(st + (uint32_t)((r0 + 64) * ROWB + q0 * 16)),
                        "r"(*(uint32_t*)&ha), "r"(*(uint32_t*)&hb),
                        "r"(*(uint32_t*)&hc), "r"(*(uint32_t*)&hd) : "memory");
    };
    auto load_B = [&](int kt) {
        const uint32_t st = sbase + (uint32_t)(kt % NSTAGE) * STAGE_B;
        const __half* wb = Wh + (size_t)(n0 + r0) * 1024 + kt * 32 + q0 * 8;
        cp_async16(st + A_BYTES + (uint32_t)(r0 * ROWB + q0 * 16), wb);
        cp_async16(st + A_BYTES + (uint32_t)((r0 + 64) * ROWB + q0 * 16),
                   wb + (size_t)64 * 1024);
    };

    // ldmatrix lane geometry (canonical m16n8k16)
    const int rA = lane & 15;
    const int cA = (lane >> 4) * 16;
    const int rB = (lane & 7) + ((lane >> 4) << 3);
    const int cB = ((lane >> 3) & 1) * 16;
    const uint32_t aBase = sbase + (uint32_t)((wm * 64 + rA) * ROWB + cA);
    const uint32_t bBase = sbase + A_BYTES + (uint32_t)((wn * 32 + rB) * ROWB + cB);

    float acc[4][4][4];
#pragma unroll
    for (int mf = 0; mf < 4; ++mf)
#pragma unroll
        for (int nf = 0; nf < 4; ++nf)
#pragma unroll
            for (int q = 0; q < 4; ++q) acc[mf][nf][q] = 0.0f;

    float4 pre[4];

    // prologue: stages 0..2 in flight, 0..1 complete before loop
    ldg_A(0, pre); load_B(0); cp_commit(); sts_A(0, pre);
    ldg_A(1, pre); load_B(1); cp_commit(); sts_A(1, pre);
    ldg_A(2, pre); load_B(2); cp_commit(); sts_A(2, pre);
    cp_wait<2>();
    __syncthreads();

    for (int kt = 0; kt < NKT; ++kt) {
        if (kt + 3 < NKT) { ldg_A(kt + 3, pre); load_B(kt + 3); cp_commit(); }

        const uint32_t soff = (uint32_t)(kt % NSTAGE) * STAGE_B;
        const uint32_t sa = aBase + soff;
        const uint32_t sb = bBase + soff;
#pragma unroll
        for (int ks = 0; ks < 2; ++ks) {
            uint32_t af[4][4];
#pragma unroll
            for (int mf = 0; mf < 4; ++mf)
                ldsm4(af[mf][0], af[mf][1], af[mf][2], af[mf][3],
                      sa + (uint32_t)(mf * 16 * ROWB + ks * 32));
            uint32_t bf[4][2];
#pragma unroll
            for (int p = 0; p < 2; ++p)
                ldsm4(bf[2 * p][0], bf[2 * p][1], bf[2 * p + 1][0],
                      bf[2 * p + 1][1], sb + (uint32_t)(p * 16 * ROWB + ks * 32));
#pragma unroll
            for (int mf = 0; mf < 4; ++mf)
#pragma unroll
                for (int nf = 0; nf < 4; ++nf)
                    mma_f16_f32(acc[mf][nf], af[mf], bf[nf]);
        }

        if (kt + 3 < NKT) sts_A(kt + 3, pre);   // buffer (kt+3)%4 == (kt-1)%4

        if (kt + 1 < NKT) {
            if (kt + 3 < NKT)      cp_wait<2>();
            else if (kt + 2 < NKT) cp_wait<1>();
            else                   cp_wait<0>();
            __syncthreads();
        }
    }

    // epilogue: bias + activation, half2 stores
    const int g   = lane >> 2;
    const int tig = lane & 3;
#pragma unroll
    for (int mf = 0; mf < 4; ++mf) {
#pragma unroll
        for (int nf = 0; nf < 4; ++nf) {
            const int row = m0 + wm * 64 + mf * 16 + g;
            const int col = n0 + wn * 32 + nf * 8 + 2 * tig;
            const float bb0 = __ldg(&bias[col]);
            const float bb1 = __ldg(&bias[col + 1]);
            float z00 = acc[mf][nf][0] + bb0;
            float z01 = acc[mf][nf][1] + bb1;
            float z10 = acc[mf][nf][2] + bb0;
            float z11 = acc[mf][nf][3] + bb1;
            float2 o0, o1;
            if (mat == 0) {        // store w = 1 - alpha = sigmoid(-z)
                o0 = make_float2(fsigmoid(-z00), fsigmoid(-z01));
                o1 = make_float2(fsigmoid(-z10), fsigmoid(-z11));
            } else {               // store v = tanh(z)
                o0 = make_float2(ftanh_fast(z00), ftanh_fast(z01));
                o1 = make_float2(ftanh_fast(z10), ftanh_fast(z11));
            }
            *(__half2*)(outp + (size_t)row * D_DIM + col)       = __float22half2_rn(o0);
            *(__half2*)(outp + (size_t)(row + 8) * D_DIM + col) = __float22half2_rn(o1);
        }
    }
}

// ---------------------------------------------------------------------------
// Sequential scan: 16384 chains, 256 CTAs x 64 threads (2 warps/CTA) so all
// 148 SMs participate (128-CTA grid left 20 SMs idle while store-throughput
// limited). Warp-autonomous cp.async rings (6 stages x 8 steps = 1KB/stage),
// both sigmoids via HW tanh.approx, a = 1 - w reconstructed in fp32.
// ---------------------------------------------------------------------------
#define SC_STEPS  8
#define SC_STG    6
#define SC_WARPS  2

__global__ __launch_bounds__(64) void scan_kernel(
    const float* __restrict__ h0,
    const float* __restrict__ dg, const float* __restrict__ bg,
    float* __restrict__ out, float* __restrict__ hout)
{
    __shared__ __align__(16) __half sbuf[SC_WARPS][SC_STG][2][SC_STEPS][32]; // 12KB

    const int tid  = (int)threadIdx.x;
    const int w    = tid >> 5;
    const int lane = tid & 31;
    const int cbase = (int)blockIdx.x * 64 + w * 32;   // warp's channel base
    const int idx   = cbase + lane;
    const int d     = idx & (D_DIM - 1);

    const float hc1 = 0.5f * dg[d];       // gate = 0.5 + 0.5*tanh(0.5*(c1*h+c0))
    const float hc0 = 0.5f * bg[d];

    float h = h0[idx];
    hout[idx] = h;

    const __half* __restrict__ Wp = g_wh;
    const __half* __restrict__ V  = g_vh;
    const uint32_t sw0 = smem_u32(&sbuf[w][0][0][0][0]);

    auto load_stage = [&](int b) {
        const uint32_t st = sw0 + (uint32_t)(b % SC_STG) * 1024u;
        const int t0 = b * SC_STEPS;
#pragma unroll
        for (int j = 0; j < 2; ++j) {
            const int c    = lane + 32 * j;
            const int arr  = c >> 5;              // 0=W, 1=V
            const int wch  = c & 31;
            const int step = wch >> 2;
            const int part = wch & 3;
            const __half* src = (arr ? V : Wp) + (size_t)(t0 + step) * BD
                                + cbase + part * 8;
            cp_async16(st + (uint32_t)(arr * 512 + step * 64 + part * 16), src);
        }
        cp_commit();
    };

#pragma unroll
    for (int s = 0; s < SC_STG - 1; ++s) load_stage(s);

    const int NB = T_DIM / SC_STEPS;      // 256
    for (int b = 0; b < NB; ++b) {
        cp_wait<SC_STG - 2>();
        __syncwarp();

        const __half* sW = &sbuf[w][b % SC_STG][0][0][0];
        const __half* sV = &sbuf[w][b % SC_STG][1][0][0];

        float a[SC_STEPS], wv[SC_STEPS];
#pragma unroll
        for (int i = 0; i < SC_STEPS; ++i) {
            const float wq = __half2float(sW[i * 32 + lane]);
            const float v  = __half2float(sV[i * 32 + lane]);
            a[i]  = 1.0f - wq;
            wv[i] = wq * v;
        }
        __syncwarp();

        if (b + SC_STG - 1 < NB) load_stage(b + SC_STG - 1);
        else cp_commit();

        const int t0 = b * SC_STEPS;
#pragma unroll
        for (int i = 0; i < SC_STEPS; ++i) {
            const float tg = tanh_hw(fmaf(hc1, h, hc0));
            const float gg = fmaf(0.5f, tg, 0.5f);
            h = fmaf(a[i], h, wv[i] * gg);
            const float sg = fmaf(0.5f, tanh_hw(0.5f * h), 0.5f);
            __stcs(&out[(size_t)(t0 + i) * BD + idx], h * h * sg);
            __stcs(&hout[(size_t)(t0 + i + 1) * BD + idx], h);
        }
    }
}

// ---------------------------------------------------------------------------
// Launch (single stream — overlap measured unprofitable in R14)
// ---------------------------------------------------------------------------
extern "C" void kernel_launch(void* const* d_in, const int* in_sizes, int n_in,
                              void* d_out, int out_size)
{
    (void)in_sizes; (void)n_in; (void)out_size;
    const float* x  = (const float*)d_in[0];   // [T,B,D]
    const float* h0 = (const float*)d_in[1];   // [B,D]
    const float* Wa = (const float*)d_in[2];   // [D,D]
    const float* ba = (const float*)d_in[3];   // [D]
    const float* Wx = (const float*)d_in[4];   // [D,D]
    const float* bv = (const float*)d_in[5];   // [D]
    const float* dg = (const float*)d_in[6];   // [D]
    const float* bg = (const float*)d_in[7];   // [D]

    float* out  = (float*)d_out;
    float* hout = out + (size_t)T_DIM * BD;

    cudaFuncSetAttribute(gemm_f16_kernel,
                         cudaFuncAttributeMaxDynamicSharedMemorySize, GEMM_SMEM);

    // 1. weights fp32 -> fp16 (X converts inside the GEMM)
    cvt_w_kernel<<<(D_DIM * D_DIM / 4) / 256, 256>>>((const float4*)Wa,
                                                     (const float4*)Wx);

    // 2. dual projections (x-fast: 16 (n,mat) CTAs share X m-tile via L2)
    dim3 grid(16, M_DIM / 128, 1);
    gemm_f16_kernel<<<grid, 256, GEMM_SMEM>>>(x, ba, bv);

    // 3. recurrence scan (256 CTAs x 64 threads: all SMs active)
    scan_kernel<<<BD / 64, 64>>>(h0, dg, bg, out, hout);
}

// round 17
// speedup vs baseline: 1.9485x; 1.0193x over previous
#include <cuda_runtime.h>
#include <cuda_fp16.h>
#include <cstdint>

// Problem dims
#define T_DIM 2048
#define B_DIM 16
#define D_DIM 1024
#define BD    16384            // B*D
#define M_DIM 32768            // T*B

// ---------------------------------------------------------------------------
// Scratch (device globals: allocation-free)
// g_wh stores w = 1 - alpha = sigmoid(-z): near 0.12 the fp16 grid is ~4x
// finer than near alpha~0.88, cutting the recurrence's dominant error term.
// ---------------------------------------------------------------------------
__device__ __half g_wh[(size_t)M_DIM * D_DIM];    // fp16 (1 - alpha)
__device__ __half g_vh[(size_t)M_DIM * D_DIM];    // fp16 v
__device__ __half g_wah[(size_t)D_DIM * D_DIM];   // fp16 W_alpha
__device__ __half g_wxh[(size_t)D_DIM * D_DIM];   // fp16 W_x

// ---------------------------------------------------------------------------
// Helpers
// ---------------------------------------------------------------------------
__device__ __forceinline__ uint32_t smem_u32(const void* p) {
    uint32_t a;
    asm("{ .reg .u64 t; cvta.to.shared.u64 t, %1; cvt.u32.u64 %0, t; }"
        : "=r"(a) : "l"(p));
    return a;
}

__device__ __forceinline__ void cp_async16(uint32_t dst, const void* src) {
    asm volatile("cp.async.cg.shared.global [%0], [%1], 16;"
                 :: "r"(dst), "l"(src) : "memory");
}
__device__ __forceinline__ void cp_commit() {
    asm volatile("cp.async.commit_group;" ::: "memory");
}
template <int N>
__device__ __forceinline__ void cp_wait() {
    asm volatile("cp.async.wait_group %0;" :: "n"(N) : "memory");
}

__device__ __forceinline__ void ldsm4(uint32_t& d0, uint32_t& d1, uint32_t& d2,
                                      uint32_t& d3, uint32_t addr) {
    asm volatile("ldmatrix.sync.aligned.m8n8.x4.shared.b16 {%0,%1,%2,%3}, [%4];"
                 : "=r"(d0), "=r"(d1), "=r"(d2), "=r"(d3)
                 : "r"(addr) : "memory");
}

__device__ __forceinline__ void mma_f16_f32(float* c, const uint32_t* a,
                                            const uint32_t* b) {
    asm volatile(
        "mma.sync.aligned.m16n8k16.row.col.f32.f16.f16.f32 "
        "{%0,%1,%2,%3}, {%4,%5,%6,%7}, {%8,%9}, {%0,%1,%2,%3};"
        : "+f"(c[0]), "+f"(c[1]), "+f"(c[2]), "+f"(c[3])
        : "r"(a[0]), "r"(a[1]), "r"(a[2]), "r"(a[3]), "r"(b[0]), "r"(b[1]));
}

__device__ __forceinline__ float fsigmoid(float z) {
    return __fdividef(1.0f, 1.0f + __expf(-z));
}
__device__ __forceinline__ float ftanh_fast(float z) {
    return 1.0f - __fdividef(2.0f, 1.0f + __expf(2.0f * z));
}
__device__ __forceinline__ float tanh_hw(float x) {
    float y;
    asm("tanh.approx.f32 %0, %1;" : "=f"(y) : "f"(x));
    return y;
}

// ---------------------------------------------------------------------------
// fp32 -> fp16 conversion for the two weight matrices (X converts in-GEMM)
// ---------------------------------------------------------------------------
__global__ __launch_bounds__(256) void cvt_w_kernel(const float4* __restrict__ wa,
                                                    const float4* __restrict__ wx) {
    const int i = (int)blockIdx.x * 256 + (int)threadIdx.x;   // n4 = 262144
    float4 v = wa[i];
    __half2 a = __float22half2_rn(make_float2(v.x, v.y));
    __half2 b = __float22half2_rn(make_float2(v.z, v.w));
    uint2 u; u.x = *(uint32_t*)&a; u.y = *(uint32_t*)&b;
    reinterpret_cast<uint2*>(g_wah)[i] = u;
    v = wx[i];
    a = __float22half2_rn(make_float2(v.x, v.y));
    b = __float22half2_rn(make_float2(v.z, v.w));
    u.x = *(uint32_t*)&a; u.y = *(uint32_t*)&b;
    reinterpret_cast<uint2*>(g_wxh)[i] = u;
}

// ---------------------------------------------------------------------------
// fp16 GEMM (verified config; HMMA pipe measured 99.4% saturated — frozen).
// CTA 128x128, BK=32, 4 stages, 8 warps (2m x 4n), warp 64x32, m16n8k16,
// fp32 accumulators. A (X): fp32 LDG -> reg cvt -> STS.128. B (W): cp.async
// fp16. mat==0 stores w = sigmoid(-z); mat==1 stores tanh(z), fp16 outputs.
// blockIdx.x in [0,16): bit3 = matrix, bits[2:0] = n-tile (x-fast: 16 CTAs
// share each X m-tile via L2).
// ---------------------------------------------------------------------------
#define NKT      32            // 1024 / 32
#define ROWB     80            // 32 halves + 8 pad
#define A_BYTES  (128 * ROWB)  // 10240
#define STAGE_B  (2 * A_BYTES) // 20480
#define NSTAGE   4
#define GEMM_SMEM (NSTAGE * STAGE_B)   // 81920

__global__ __launch_bounds__(256, 2) void gemm_f16_kernel(
    const float* __restrict__ X,
    const float* __restrict__ ba, const float* __restrict__ bv)
{
    extern __shared__ char smem_raw[];
    const uint32_t sbase = smem_u32(smem_raw);

    const int tid  = (int)threadIdx.x;
    const int warp = tid >> 5;
    const int lane = tid & 31;
    const int wm   = warp >> 2;            // 0..1
    const int wn   = warp & 3;             // 0..3

    const int nm  = (int)blockIdx.x;       // 0..15
    const int mat = nm >> 3;
    const int n0  = (nm & 7) * 128;
    const int m0  = (int)blockIdx.y * 128;

    const __half* __restrict__ Wh  = mat ? g_wxh : g_wah;
    const float* __restrict__ bias = mat ? bv : ba;
    __half* __restrict__ outp      = mat ? g_vh : g_wh;

    const int r0 = tid >> 2;               // 0..63
    const int q0 = tid & 3;

    const float4* __restrict__ Xv = reinterpret_cast<const float4*>(X);

    auto ldg_A = [&](int kt, float4* r) {
        const size_t base = (size_t)(m0 + r0) * 256 + (size_t)(kt * 8 + q0 * 2);
        r[0] = __ldg(Xv + base);
        r[1] = __ldg(Xv + base + 1);
        r[2] = __ldg(Xv + base + (size_t)64 * 256);
        r[3] = __ldg(Xv + base + (size_t)64 * 256 + 1);
    };
    auto sts_A = [&](int kt, const float4* r) {
        const uint32_t st = sbase + (uint32_t)(kt % NSTAGE) * STAGE_B;
        __half2 ha = __float22half2_rn(make_float2(r[0].x, r[0].y));
        __half2 hb = __float22half2_rn(make_float2(r[0].z, r[0].w));
        __half2 hc = __float22half2_rn(make_float2(r[1].x, r[1].y));
        __half2 hd = __float22half2_rn(make_float2(r[1].z, r[1].w));
        asm volatile("st.shared.v4.b32 [%0], {%1,%2,%3,%4};"
                     :: "r"(st + (uint32_t)(r0 * ROWB + q0 * 16)),
                        "r"(*(uint32_t*)&ha), "r"(*(uint32_t*)&hb),
                        "r"(*(uint32_t*)&hc), "r"(*(uint32_t*)&hd) : "memory");
        ha = __float22half2_rn(make_float2(r[2].x, r[2].y));
        hb = __float22half2_rn(make_float2(r[2].z, r[2].w));
        hc = __float22half2_rn(make_float2(r[3].x, r[3].y));
        hd = __float22half2_rn(make_float2(r[3].z, r[3].w));
        asm volatile("st.shared.v4.b32 [%0], {%1,%2,%3,%4};"
                     :: "r"(st + (uint32_t)((r0 + 64) * ROWB + q0 * 16)),
                        "r"(*(uint32_t*)&ha), "r"(*(uint32_t*)&hb),
                        "r"(*(uint32_t*)&hc), "r"(*(uint32_t*)&hd) : "memory");
    };
    auto load_B = [&](int kt) {
        const uint32_t st = sbase + (uint32_t)(kt % NSTAGE) * STAGE_B;
        const __half* wb = Wh + (size_t)(n0 + r0) * 1024 + kt * 32 + q0 * 8;
        cp_async16(st + A_BYTES + (uint32_t)(r0 * ROWB + q0 * 16), wb);
        cp_async16(st + A_BYTES + (uint32_t)((r0 + 64) * ROWB + q0 * 16),
                   wb + (size_t)64 * 1024);
    };

    // ldmatrix lane geometry (canonical m16n8k16)
    const int rA = lane & 15;
    const int cA = (lane >> 4) * 16;
    const int rB = (lane & 7) + ((lane >> 4) << 3);
    const int cB = ((lane >> 3) & 1) * 16;
    const uint32_t aBase = sbase + (uint32_t)((wm * 64 + rA) * ROWB + cA);
    const uint32_t bBase = sbase + A_BYTES + (uint32_t)((wn * 32 + rB) * ROWB + cB);

    float acc[4][4][4];
#pragma unroll
    for (int mf = 0; mf < 4; ++mf)
#pragma unroll
        for (int nf = 0; nf < 4; ++nf)
#pragma unroll
            for (int q = 0; q < 4; ++q) acc[mf][nf][q] = 0.0f;

    float4 pre[4];

    // prologue: stages 0..2 in flight, 0..1 complete before loop
    ldg_A(0, pre); load_B(0); cp_commit(); sts_A(0, pre);
    ldg_A(1, pre); load_B(1); cp_commit(); sts_A(1, pre);
    ldg_A(2, pre); load_B(2); cp_commit(); sts_A(2, pre);
    cp_wait<2>();
    __syncthreads();

    for (int kt = 0; kt < NKT; ++kt) {
        if (kt + 3 < NKT) { ldg_A(kt + 3, pre); load_B(kt + 3); cp_commit(); }

        const uint32_t soff = (uint32_t)(kt % NSTAGE) * STAGE_B;
        const uint32_t sa = aBase + soff;
        const uint32_t sb = bBase + soff;
#pragma unroll
        for (int ks = 0; ks < 2; ++ks) {
            uint32_t af[4][4];
#pragma unroll
            for (int mf = 0; mf < 4; ++mf)
                ldsm4(af[mf][0], af[mf][1], af[mf][2], af[mf][3],
                      sa + (uint32_t)(mf * 16 * ROWB + ks * 32));
            uint32_t bf[4][2];
#pragma unroll
            for (int p = 0; p < 2; ++p)
                ldsm4(bf[2 * p][0], bf[2 * p][1], bf[2 * p + 1][0],
                      bf[2 * p + 1][1], sb + (uint32_t)(p * 16 * ROWB + ks * 32));
#pragma unroll
            for (int mf = 0; mf < 4; ++mf)
#pragma unroll
                for (int nf = 0; nf < 4; ++nf)
                    mma_f16_f32(acc[mf][nf], af[mf], bf[nf]);
        }

        if (kt + 3 < NKT) sts_A(kt + 3, pre);   // buffer (kt+3)%4 == (kt-1)%4

        if (kt + 1 < NKT) {
            if (kt + 3 < NKT)      cp_wait<2>();
            else if (kt + 2 < NKT) cp_wait<1>();
            else                   cp_wait<0>();
            __syncthreads();
        }
    }

    // epilogue: bias + activation, half2 stores
    const int g   = lane >> 2;
    const int tig = lane & 3;
#pragma unroll
    for (int mf = 0; mf < 4; ++mf) {
#pragma unroll
        for (int nf = 0; nf < 4; ++nf) {
            const int row = m0 + wm * 64 + mf * 16 + g;
            const int col = n0 + wn * 32 + nf * 8 + 2 * tig;
            const float bb0 = __ldg(&bias[col]);
            const float bb1 = __ldg(&bias[col + 1]);
            float z00 = acc[mf][nf][0] + bb0;
            float z01 = acc[mf][nf][1] + bb1;
            float z10 = acc[mf][nf][2] + bb0;
            float z11 = acc[mf][nf][3] + bb1;
            float2 o0, o1;
            if (mat == 0) {        // store w = 1 - alpha = sigmoid(-z)
                o0 = make_float2(fsigmoid(-z00), fsigmoid(-z01));
                o1 = make_float2(fsigmoid(-z10), fsigmoid(-z11));
            } else {               // store v = tanh(z)
                o0 = make_float2(ftanh_fast(z00), ftanh_fast(z01));
                o1 = make_float2(ftanh_fast(z10), ftanh_fast(z11));
            }
            *(__half2*)(outp + (size_t)row * D_DIM + col)       = __float22half2_rn(o0);
            *(__half2*)(outp + (size_t)(row + 8) * D_DIM + col) = __float22half2_rn(o1);
        }
    }
}

// ---------------------------------------------------------------------------
// Sequential scan: 16384 chains, 512 CTAs x 32 threads (1 warp/CTA, ~3.5
// CTAs/SM) — maximizes outstanding-store concurrency against the HBM write
// drain, which R16 showed is the binding constraint. 8-stage cp.async ring
// (1KB/stage) absorbs store-backpressure jitter on the loads. Both sigmoids
// via HW tanh.approx; a = 1 - w reconstructed in fp32.
// ---------------------------------------------------------------------------
#define SC_STEPS  8
#define SC_STG    8

__global__ __launch_bounds__(32) void scan_kernel(
    const float* __restrict__ h0,
    const float* __restrict__ dg, const float* __restrict__ bg,
    float* __restrict__ out, float* __restrict__ hout)
{
    __shared__ __align__(16) __half sbuf[SC_STG][2][SC_STEPS][32];  // 8KB

    const int lane  = (int)threadIdx.x;
    const int cbase = (int)blockIdx.x * 32;            // warp's channel base
    const int idx   = cbase + lane;
    const int d     = idx & (D_DIM - 1);

    const float hc1 = 0.5f * dg[d];       // gate = 0.5 + 0.5*tanh(0.5*(c1*h+c0))
    const float hc0 = 0.5f * bg[d];

    float h = h0[idx];
    hout[idx] = h;

    const __half* __restrict__ Wp = g_wh;
    const __half* __restrict__ V  = g_vh;
    const uint32_t sw0 = smem_u32(&sbuf[0][0][0][0]);

    auto load_stage = [&](int b) {
        const uint32_t st = sw0 + (uint32_t)(b % SC_STG) * 1024u;
        const int t0 = b * SC_STEPS;
#pragma unroll
        for (int j = 0; j < 2; ++j) {
            const int c    = lane + 32 * j;
            const int arr  = c >> 5;              // 0=W, 1=V
            const int wch  = c & 31;
            const int step = wch >> 2;
            const int part = wch & 3;
            const __half* src = (arr ? V : Wp) + (size_t)(t0 + step) * BD
                                + cbase + part * 8;
            cp_async16(st + (uint32_t)(arr * 512 + step * 64 + part * 16), src);
        }
        cp_commit();
    };

#pragma unroll
    for (int s = 0; s < SC_STG - 1; ++s) load_stage(s);

    const int NB = T_DIM / SC_STEPS;      // 256
    for (int b = 0; b < NB; ++b) {
        cp_wait<SC_STG - 2>();
        __syncwarp();

        const __half* sW = &sbuf[b % SC_STG][0][0][0];
        const __half* sV = &sbuf[b % SC_STG][1][0][0];

        float a[SC_STEPS], wv[SC_STEPS];
#pragma unroll
        for (int i = 0; i < SC_STEPS; ++i) {
            const float wq = __half2float(sW[i * 32 + lane]);
            const float v  = __half2float(sV[i * 32 + lane]);
            a[i]  = 1.0f - wq;
            wv[i] = wq * v;
        }
        __syncwarp();

        if (b + SC_STG - 1 < NB) load_stage(b + SC_STG - 1);
        else cp_commit();

        const int t0 = b * SC_STEPS;
#pragma unroll
        for (int i = 0; i < SC_STEPS; ++i) {
            const float tg = tanh_hw(fmaf(hc1, h, hc0));
            const float gg = fmaf(0.5f, tg, 0.5f);
            h = fmaf(a[i], h, wv[i] * gg);
            const float sg = fmaf(0.5f, tanh_hw(0.5f * h), 0.5f);
            __stcs(&out[(size_t)(t0 + i) * BD + idx], h * h * sg);
            __stcs(&hout[(size_t)(t0 + i + 1) * BD + idx], h);
        }
    }
}

// ---------------------------------------------------------------------------
// Launch (single stream — overlap measured unprofitable in R14)
// ---------------------------------------------------------------------------
extern "C" void kernel_launch(void* const* d_in, const int* in_sizes, int n_in,
                              void* d_out, int out_size)
{
    (void)in_sizes; (void)n_in; (void)out_size;
    const float* x  = (const float*)d_in[0];   // [T,B,D]
    const float* h0 = (const float*)d_in[1];   // [B,D]
    const float* Wa = (const float*)d_in[2];   // [D,D]
    const float* ba = (const float*)d_in[3];   // [D]
    const float* Wx = (const float*)d_in[4];   // [D,D]
    const float* bv = (const float*)d_in[5];   // [D]
    const float* dg = (const float*)d_in[6];   // [D]
    const float* bg = (const float*)d_in[7];   // [D]

    float* out  = (float*)d_out;
    float* hout = out + (size_t)T_DIM * BD;

    cudaFuncSetAttribute(gemm_f16_kernel,
                         cudaFuncAttributeMaxDynamicSharedMemorySize, GEMM_SMEM);

    // 1. weights fp32 -> fp16 (X converts inside the GEMM)
    cvt_w_kernel<<<(D_DIM * D_DIM / 4) / 256, 256>>>((const float4*)Wa,
                                                     (const float4*)Wx);

    // 2. dual projections (x-fast: 16 (n,mat) CTAs share X m-tile via L2)
    dim3 grid(16, M_DIM / 128, 1);
    gemm_f16_kernel<<<grid, 256, GEMM_SMEM>>>(x, ba, bv);

    // 3. recurrence scan (512 CTAs x 32: max store concurrency per SM)
    scan_kernel<<<BD / 32, 32>>>(h0, dg, bg, out, hout);
}